// round 9
// baseline (speedup 1.0000x reference)
#include <cuda_runtime.h>
#include <cuda_bf16.h>
#include <math.h>

#define S_LEN 120
#define T_LEN 10
#define B_SZ  128
#define E_DIM 80
#define HW    75
#define HWP   76
#define HS    700
#define NW    (S_LEN * B_SZ)   /* 15360 word-level batch */

typedef __nv_bfloat16 bf;

#define XE_N    (T_LEN * NW * E_DIM)
#define XW_N    (2L * T_LEN * NW * (3 * HW))   /* fp32; sentence xw reuse fits */
#define Y0W_N   (T_LEN * NW * 2 * HW)
#define WORDS_N (NW * 4 * HW)
#define Y0S_N   ((long)S_LEN * B_SZ * 2 * HS)
#define HWBUF_N (2 * NW * HWP)
#define HSBUF_N (2 * B_SZ * HS)

#define NBLK_S  88            /* persistent sentence kernel: 2 dirs x 44 hc tiles */
#define WSTRW   356           /* u32 stride of W smem row */
#define HSTRW   12            /* u32 stride of h staging row */
#define SMEM_PERS ((2 * 48 * WSTRW + 2 * 2 * 128 * HSTRW) * 4)   /* 161280 B */

#define GSTR    40            /* bf stride of GEMM smem row (80B, 16B aligned) */
#define GEMM_SMEM (2 * 4 * 128 * GSTR * 2)   /* 81920 B */

/* ---------------- persistent scratch (device globals; no allocs) ------------- */
__device__ bf    g_xe_b[XE_N],    g_xe_s[XE_N];
__device__ float g_xw[XW_N];
__device__ bf    g_y0w_b[Y0W_N],  g_y0w_s[Y0W_N];
__device__ bf    g_words_b[WORDS_N], g_words_s[WORDS_N];
__device__ bf    g_y0s_b[Y0S_N],  g_y0s_s[Y0S_N];
__device__ float g_hwf[4][HWBUF_N];
__device__ bf    g_hwb[4][HWBUF_N], g_hws[4][HWBUF_N];
__device__ float g_hsf[4][HSBUF_N];
__device__ bf    g_hsb[4][HSBUF_N], g_hss[4][HSBUF_N];
__device__ unsigned g_bar;
/* weight splits */
__device__ bf g_weWih0_b[2*3*HW*E_DIM],  g_weWih0_s[2*3*HW*E_DIM];
__device__ bf g_weWih1_b[2*3*HW*2*HW],   g_weWih1_s[2*3*HW*2*HW];
__device__ bf g_weWhh0_b[2*3*HW*HWP],    g_weWhh0_s[2*3*HW*HWP];
__device__ bf g_weWhh1_b[2*3*HW*HWP],    g_weWhh1_s[2*3*HW*HWP];
__device__ bf g_seWih0_b[2*3*HS*4*HW],   g_seWih0_s[2*3*HS*4*HW];
__device__ bf g_seWih1_b[2*3*HS*2*HS],   g_seWih1_s[2*3*HS*2*HS];
__device__ bf g_seWhh0_b[2*3*HS*HS],     g_seWhh0_s[2*3*HS*HS];
__device__ bf g_seWhh1_b[2*3*HS*HS],     g_seWhh1_s[2*3*HS*HS];

/* ---------------- helpers ---------------------------------------------------- */
__device__ __forceinline__ void bsplit(float v, bf &b, bf &s) {
    b = __float2bfloat16_rn(v);
    s = __float2bfloat16_rn(v - __bfloat162float(b));
}
__device__ __forceinline__ void mma16(float d[4], const unsigned a[4],
                                      unsigned b0, unsigned b1) {
    asm volatile(
        "mma.sync.aligned.m16n8k16.row.col.f32.bf16.bf16.f32 "
        "{%0,%1,%2,%3},{%4,%5,%6,%7},{%8,%9},{%0,%1,%2,%3};"
        : "+f"(d[0]), "+f"(d[1]), "+f"(d[2]), "+f"(d[3])
        : "r"(a[0]), "r"(a[1]), "r"(a[2]), "r"(a[3]), "r"(b0), "r"(b1));
}
__device__ __forceinline__ void cpasync4(unsigned saddr, const void* g, bool p) {
    asm volatile("cp.async.ca.shared.global [%0], [%1], 4, %2;"
                 :: "r"(saddr), "l"(g), "r"(p ? 4u : 0u));
}
__device__ __forceinline__ void cp_commit() {
    asm volatile("cp.async.commit_group;");
}
__device__ __forceinline__ void cp_wait1() {
    asm volatile("cp.async.wait_group 1;");
}
__device__ __forceinline__ void cp_wait0() {
    asm volatile("cp.async.wait_group 0;");
}

/* ---------------- weight split: fp32 [rows,K] -> bf16 big/small [rows,KP] ---- */
__global__ void split_k(const float* __restrict__ W, bf* __restrict__ b,
                        bf* __restrict__ s, int rows, int K, int KP) {
    long idx = blockIdx.x * 256L + threadIdx.x;
    if (idx >= (long)rows * KP) return;
    int k = (int)(idx % KP);
    long r = idx / KP;
    float v = (k < K) ? W[r * K + k] : 0.f;
    bf vb, vs; bsplit(v, vb, vs);
    b[idx] = vb; s[idx] = vs;
}

/* ---------------- embedding gather + split ----------------------------------- */
__global__ void embed_split_k(const int* __restrict__ x, const float* __restrict__ emb,
                              bf* __restrict__ xb, bf* __restrict__ xs) {
    long idx = blockIdx.x * 256L + threadIdx.x;
    if (idx >= XE_N) return;
    int e = (int)(idx % E_DIM);
    int n = (int)((idx / E_DIM) % NW);
    int t = (int)(idx / ((long)E_DIM * NW));
    int s = n >> 7, bb_ = n & 127;
    int tok = x[(s * T_LEN + t) * B_SZ + bb_];
    float v = emb[(long)tok * E_DIM + e];
    bf vb, vs; bsplit(v, vb, vs);
    xb[idx] = vb; xs[idx] = vs;
}

/* -------- C[m][g] = bias[g] + A[m,:]·W[g,:]  (split A & W, 3-mma) ------------
   Tile 128x128, BK=32 bf, 256 thr (8 warps, 4x2 -> warp tile 32x64).
   cp.async double-buffered smem; stride-40 bf rows (16B aligned, no conflicts). */
__global__ __launch_bounds__(256) void mma_gemm_bias(
    const bf* __restrict__ Ab_g, const bf* __restrict__ As_g,
    const bf* __restrict__ Wb_g, const bf* __restrict__ Ws_g,
    const float* __restrict__ bias, float* __restrict__ C,
    int M, int G, int K)
{
    extern __shared__ __align__(16) bf gsm[];   /* [2 buf][4 arr][128][GSTR] */
    unsigned sbase = (unsigned)__cvta_generic_to_shared(gsm);
    int tid = threadIdx.x, lane = tid & 31, wid = tid >> 5;
    int gid = lane >> 2, tig = lane & 3;
    int wm = wid & 3, wn = wid >> 2;
    int row0 = blockIdx.y * 128, col0 = blockIdx.x * 128;

    float acc[2][8][4];
#pragma unroll
    for (int mt = 0; mt < 2; mt++)
#pragma unroll
        for (int nt = 0; nt < 8; nt++)
#pragma unroll
            for (int i = 0; i < 4; i++) acc[mt][nt][i] = 0.f;

    auto fill = [&](int buf, int k0) {
#pragma unroll
        for (int j = 0; j < 32; j++) {
            int e = j * 256 + tid;
            int arr = e >> 11;            /* 0..3: Ab, As, Wb, Ws */
            int rem = e & 2047;
            int row = rem >> 4, kk = rem & 15;
            int gk = k0 + 2 * kk;
            unsigned sa = sbase + (unsigned)((((buf * 4 + arr) * 128 + row) * (GSTR/2) + kk) * 4);
            const bf* gp; bool v;
            if (arr < 2) {
                v = (gk < K) && (row0 + row < M);
                gp = (arr ? As_g : Ab_g) + (v ? ((long)(row0 + row) * K + gk) : 0);
            } else {
                int gc = col0 + row;
                v = (gk < K) && (gc < G);
                gp = (arr == 2 ? Wb_g : Ws_g) + (v ? ((long)gc * K + gk) : 0);
            }
            cpasync4(sa, gp, v);
        }
        cp_commit();
    };

    fill(0, 0);
    int buf = 0;
    for (int k0 = 0; k0 < K; k0 += 32) {
        bool more = (k0 + 32 < K);
        if (more) fill(1 - buf, k0 + 32);
        if (more) cp_wait1(); else cp_wait0();
        __syncthreads();

        const unsigned* sAb = (const unsigned*)(gsm + (long)(buf * 4 + 0) * 128 * GSTR);
        const unsigned* sAs = (const unsigned*)(gsm + (long)(buf * 4 + 1) * 128 * GSTR);
        const unsigned* sWb = (const unsigned*)(gsm + (long)(buf * 4 + 2) * 128 * GSTR);
        const unsigned* sWs = (const unsigned*)(gsm + (long)(buf * 4 + 3) * 128 * GSTR);
#pragma unroll
        for (int half = 0; half < 2; half++) {
            int base = half * 8;
            unsigned ab[2][4], as_[2][4];
#pragma unroll
            for (int mt = 0; mt < 2; mt++) {
                int mr = wm * 32 + mt * 16;
                const unsigned* p0b = sAb + (mr + gid) * (GSTR/2);
                const unsigned* p1b = sAb + (mr + gid + 8) * (GSTR/2);
                const unsigned* p0s = sAs + (mr + gid) * (GSTR/2);
                const unsigned* p1s = sAs + (mr + gid + 8) * (GSTR/2);
                ab[mt][0] = p0b[base + tig];      ab[mt][1] = p1b[base + tig];
                ab[mt][2] = p0b[base + tig + 4];  ab[mt][3] = p1b[base + tig + 4];
                as_[mt][0] = p0s[base + tig];     as_[mt][1] = p1s[base + tig];
                as_[mt][2] = p0s[base + tig + 4]; as_[mt][3] = p1s[base + tig + 4];
            }
#pragma unroll
            for (int nt = 0; nt < 8; nt++) {
                int nr = wn * 64 + nt * 8 + gid;
                const unsigned* pb = sWb + nr * (GSTR/2);
                const unsigned* ps = sWs + nr * (GSTR/2);
                unsigned bb0 = pb[base + tig], bb1 = pb[base + tig + 4];
                unsigned bs0 = ps[base + tig], bs1 = ps[base + tig + 4];
#pragma unroll
                for (int mt = 0; mt < 2; mt++) {
                    mma16(acc[mt][nt], ab[mt], bb0, bb1);
                    mma16(acc[mt][nt], ab[mt], bs0, bs1);
                    mma16(acc[mt][nt], as_[mt], bb0, bb1);
                }
            }
        }
        __syncthreads();
        buf = 1 - buf;
    }
#pragma unroll
    for (int mt = 0; mt < 2; mt++)
#pragma unroll
        for (int nt = 0; nt < 8; nt++)
#pragma unroll
            for (int i = 0; i < 4; i++) {
                int gr = row0 + wm * 32 + mt * 16 + gid + 8 * (i >> 1);
                int gc = col0 + wn * 64 + nt * 8 + tig * 2 + (i & 1);
                if (gr < M && gc < G)
                    C[(long)gr * G + gc] = acc[mt][nt][i] + bias[gc];
            }
}

/* -------- word GRU step (3-mma split, per-step launch) ----------------------- */
__global__ __launch_bounds__(128) void gru_step_mma(
    const float* __restrict__ hf_in, const bf* __restrict__ hb_in,
    const bf* __restrict__ hs_in,
    float* __restrict__ hf_out, bf* __restrict__ hb_out, bf* __restrict__ hs_out,
    const float* __restrict__ xw, const bf* __restrict__ Whh_b,
    const bf* __restrict__ Whh_s, const float* __restrict__ bhh,
    bf* __restrict__ y_b, bf* __restrict__ y_s,
    int H, int KP, int Nb, int T, int t_f, int t_b)
{
    __shared__ __align__(16) bf Hsm[2][64][20];
    __shared__ __align__(16) bf Wsm[2][48][20];
    int tid = threadIdx.x, lane = tid & 31, wid = tid >> 5;
    int gid = lane >> 2, tig = lane & 3;
    int r0 = blockIdx.x * 64;
    int dir = r0 / Nb;
    int n0 = r0 - dir * Nb;
    int h0 = blockIdx.y * 16;
    const bf* Wdb = Whh_b + (long)dir * 3 * H * KP;
    const bf* Wds = Whh_s + (long)dir * 3 * H * KP;
    const bf* hbd = hb_in + ((long)dir * Nb + n0) * KP;
    const bf* hsd = hs_in + ((long)dir * Nb + n0) * KP;

    float acc[6][4];
#pragma unroll
    for (int nt = 0; nt < 6; nt++)
#pragma unroll
        for (int i = 0; i < 4; i++) acc[nt][i] = 0.f;

    unsigned ph[2][4], pw[2][3];
    auto fetch = [&](int k0) {
#pragma unroll
        for (int j = 0; j < 4; j++) {
            int e = tid + j * 128, r = e >> 3, kk = e & 7;
            int gk = k0 + 2 * kk;
            bool v = (gk < KP);
            long off = (long)r * KP + gk;
            ph[0][j] = v ? *(const unsigned*)(hbd + off) : 0u;
            ph[1][j] = v ? *(const unsigned*)(hsd + off) : 0u;
        }
#pragma unroll
        for (int j = 0; j < 3; j++) {
            int e = tid + j * 128, r = e >> 3, kk = e & 7;
            int gate = r >> 4, hh = r & 15;
            int gk = k0 + 2 * kk;
            bool v = (gk < KP) && (h0 + hh < H);
            long off = ((long)gate * H + h0 + hh) * KP + gk;
            pw[0][j] = v ? *(const unsigned*)(Wdb + off) : 0u;
            pw[1][j] = v ? *(const unsigned*)(Wds + off) : 0u;
        }
    };
    fetch(0);
    for (int k0 = 0; k0 < KP; k0 += 16) {
#pragma unroll
        for (int j = 0; j < 4; j++) {
            int e = tid + j * 128, r = e >> 3, kk = e & 7;
            ((unsigned*)Hsm[0][r])[kk] = ph[0][j];
            ((unsigned*)Hsm[1][r])[kk] = ph[1][j];
        }
#pragma unroll
        for (int j = 0; j < 3; j++) {
            int e = tid + j * 128, r = e >> 3, kk = e & 7;
            ((unsigned*)Wsm[0][r])[kk] = pw[0][j];
            ((unsigned*)Wsm[1][r])[kk] = pw[1][j];
        }
        __syncthreads();
        if (k0 + 16 < KP) fetch(k0 + 16);
        int mr = wid * 16;
        unsigned ab[4], as_[4];
        {
            const unsigned* p0b = (const unsigned*)Hsm[0][mr + gid];
            const unsigned* p1b = (const unsigned*)Hsm[0][mr + gid + 8];
            const unsigned* p0s = (const unsigned*)Hsm[1][mr + gid];
            const unsigned* p1s = (const unsigned*)Hsm[1][mr + gid + 8];
            ab[0] = p0b[tig];      ab[1] = p1b[tig];
            ab[2] = p0b[tig + 4];  ab[3] = p1b[tig + 4];
            as_[0] = p0s[tig];     as_[1] = p1s[tig];
            as_[2] = p0s[tig + 4]; as_[3] = p1s[tig + 4];
        }
#pragma unroll
        for (int nt = 0; nt < 6; nt++) {
            const unsigned* pb = (const unsigned*)Wsm[0][nt * 8 + gid];
            const unsigned* ps = (const unsigned*)Wsm[1][nt * 8 + gid];
            unsigned bb0 = pb[tig], bb1 = pb[tig + 4];
            unsigned bs0 = ps[tig], bs1 = ps[tig + 4];
            mma16(acc[nt], ab, bb0, bb1);
            mma16(acc[nt], ab, bs0, bs1);
            mma16(acc[nt], as_, bb0, bb1);
        }
        __syncthreads();
    }

    int t = dir ? t_b : t_f;
#pragma unroll
    for (int nt = 0; nt < 2; nt++)
#pragma unroll
        for (int i = 0; i < 4; i++) {
            int n = n0 + wid * 16 + gid + 8 * (i >> 1);
            int hc = h0 + nt * 8 + tig * 2 + (i & 1);
            if (hc >= H) continue;
            float br = bhh[dir * 3 * H + hc];
            float bz = bhh[dir * 3 * H + H + hc];
            float bn = bhh[dir * 3 * H + 2 * H + hc];
            long xb = ((long)(dir * T + t) * Nb + n) * (3 * H);
            float xr = xw[xb + hc];
            float xz = xw[xb + H + hc];
            float xn = xw[xb + 2 * H + hc];
            float gr_ = acc[nt][i] + br;
            float gz_ = acc[nt + 2][i] + bz;
            float gn_ = acc[nt + 4][i] + bn;
            float rg = 1.f / (1.f + expf(-(xr + gr_)));
            float zg = 1.f / (1.f + expf(-(xz + gz_)));
            float ng = tanhf(xn + rg * gn_);
            long hidx = ((long)dir * Nb + n) * KP + hc;
            float hp = hf_in[hidx];
            float hn = (1.f - zg) * ng + zg * hp;
            hf_out[hidx] = hn;
            bf hb_, hs_; bsplit(hn, hb_, hs_);
            hb_out[hidx] = hb_;
            hs_out[hidx] = hs_;
            if (y_b) {
                long yi = ((long)t * Nb + n) * 2 * H + (long)dir * H + hc;
                y_b[yi] = hb_; y_s[yi] = hs_;
            }
        }
}

/* -------- persistent sentence GRU: 120 steps, Whh slice cached in SMEM ------- */
__global__ __launch_bounds__(256) void gru_sent_persistent(
    const bf* __restrict__ Whh_b, const bf* __restrict__ Whh_s,
    const float* __restrict__ bhh, const float* __restrict__ xw,
    float* __restrict__ hfA, bf* __restrict__ hbA, bf* __restrict__ hsA,
    float* __restrict__ hfB, bf* __restrict__ hbB, bf* __restrict__ hsB,
    bf* __restrict__ y_b, bf* __restrict__ y_s, unsigned* __restrict__ bar)
{
    extern __shared__ __align__(16) unsigned smem_u[];
    unsigned* Wu  = smem_u;                        /* [2][48][WSTRW] */
    unsigned* Hst = smem_u + 2 * 48 * WSTRW;       /* [2buf][2arr][128][HSTRW] */

    int tid = threadIdx.x, lane = tid & 31, wid = tid >> 5;
    int gid = lane >> 2, tig = lane & 3;
    int dir = blockIdx.x / 44;
    int h0 = (blockIdx.x % 44) * 16;

    for (int e = tid; e < 2 * 48 * 352; e += 256) {
        int arr = e / (48 * 352);
        int rem = e % (48 * 352);
        int r = rem / 352, w = rem % 352;
        int gate = r >> 4, hc = h0 + (r & 15);
        unsigned v = 0;
        if (w < 350 && hc < HS) {
            const bf* src = (arr ? Whh_s : Whh_b) +
                            (((long)dir * 3 + gate) * HS + hc) * (long)HS + 2 * w;
            v = *(const unsigned*)src;
        }
        Wu[(long)arr * 48 * WSTRW + r * WSTRW + w] = v;
    }
    __syncthreads();

    unsigned ph[8];
    for (int s = 0; s < S_LEN; s++) {
        const float* hf_in = (s & 1) ? hfB : hfA;
        const bf*    hb_in = (s & 1) ? hbB : hbA;
        const bf*    hs_in = (s & 1) ? hsB : hsA;
        float* hf_out = (s & 1) ? hfA : hfB;
        bf*    hb_out = (s & 1) ? hbA : hbB;
        bf*    hs_out = (s & 1) ? hsA : hsB;

        float acc[6][4];
#pragma unroll
        for (int nt = 0; nt < 6; nt++)
#pragma unroll
            for (int i = 0; i < 4; i++) acc[nt][i] = 0.f;

#pragma unroll
        for (int j = 0; j < 8; j++) {
            int e = tid + j * 256, arr = e >> 10, rem = e & 1023;
            int row = rem >> 3, w = rem & 7;
            const bf* hp = arr ? hs_in : hb_in;
            ph[j] = (w < 350) ? *(const unsigned*)(hp + ((long)dir * 128 + row) * HS + 2 * w)
                              : 0u;
        }
        for (int it = 0; it < 44; it++) {
            int buf = it & 1;
#pragma unroll
            for (int j = 0; j < 8; j++) {
                int e = tid + j * 256, arr = e >> 10, rem = e & 1023;
                int row = rem >> 3, w = rem & 7;
                Hst[((buf * 2 + arr) * 128 + row) * HSTRW + w] = ph[j];
            }
            if (it + 1 < 44) {
                int g0 = (it + 1) * 8;
#pragma unroll
                for (int j = 0; j < 8; j++) {
                    int e = tid + j * 256, arr = e >> 10, rem = e & 1023;
                    int row = rem >> 3, w = rem & 7;
                    int g = g0 + w;
                    const bf* hp = arr ? hs_in : hb_in;
                    ph[j] = (g < 350) ? *(const unsigned*)(hp + ((long)dir * 128 + row) * HS + 2 * g)
                                      : 0u;
                }
            }
            __syncthreads();
            int mrow = wid * 16;
            unsigned ab[4], as_[4];
            {
                const unsigned* p0b = Hst + ((buf * 2 + 0) * 128 + mrow + gid) * HSTRW;
                const unsigned* p1b = Hst + ((buf * 2 + 0) * 128 + mrow + gid + 8) * HSTRW;
                const unsigned* p0s = Hst + ((buf * 2 + 1) * 128 + mrow + gid) * HSTRW;
                const unsigned* p1s = Hst + ((buf * 2 + 1) * 128 + mrow + gid + 8) * HSTRW;
                ab[0] = p0b[tig];      ab[1] = p1b[tig];
                ab[2] = p0b[tig + 4];  ab[3] = p1b[tig + 4];
                as_[0] = p0s[tig];     as_[1] = p1s[tig];
                as_[2] = p0s[tig + 4]; as_[3] = p1s[tig + 4];
            }
            int kb = it * 8;
#pragma unroll
            for (int nt = 0; nt < 6; nt++) {
                const unsigned* pb = Wu + (nt * 8 + gid) * WSTRW + kb;
                const unsigned* ps = Wu + (long)48 * WSTRW + (nt * 8 + gid) * WSTRW + kb;
                unsigned bb0 = pb[tig], bb1 = pb[tig + 4];
                unsigned bs0 = ps[tig], bs1 = ps[tig + 4];
                mma16(acc[nt], ab, bb0, bb1);
                mma16(acc[nt], ab, bs0, bs1);
                mma16(acc[nt], as_, bb0, bb1);
            }
        }

        int t = dir ? (S_LEN - 1 - s) : s;
#pragma unroll
        for (int nt = 0; nt < 2; nt++)
#pragma unroll
            for (int i = 0; i < 4; i++) {
                int n = wid * 16 + gid + 8 * (i >> 1);
                int hc = h0 + nt * 8 + tig * 2 + (i & 1);
                if (hc >= HS) continue;
                float br = bhh[dir * 3 * HS + hc];
                float bz = bhh[dir * 3 * HS + HS + hc];
                float bn = bhh[dir * 3 * HS + 2 * HS + hc];
                long xb = ((long)(dir * S_LEN + t) * 128 + n) * (3 * HS);
                float xr = xw[xb + hc];
                float xz = xw[xb + HS + hc];
                float xn = xw[xb + 2 * HS + hc];
                float gr_ = acc[nt][i] + br;
                float gz_ = acc[nt + 2][i] + bz;
                float gn_ = acc[nt + 4][i] + bn;
                float rg = 1.f / (1.f + expf(-(xr + gr_)));
                float zg = 1.f / (1.f + expf(-(xz + gz_)));
                float ng = tanhf(xn + rg * gn_);
                long hidx = ((long)dir * 128 + n) * HS + hc;
                float hp = hf_in[hidx];
                float hn = (1.f - zg) * ng + zg * hp;
                hf_out[hidx] = hn;
                bf hb_, hs_; bsplit(hn, hb_, hs_);
                hb_out[hidx] = hb_;
                hs_out[hidx] = hs_;
                if (y_b) {
                    long yi = ((long)t * 128 + n) * 2 * HS + (long)dir * HS + hc;
                    y_b[yi] = hb_; y_s[yi] = hs_;
                }
            }

        __syncthreads();
        if (tid == 0) {
            __threadfence();
            atomicAdd(bar, 1u);
            unsigned target = (unsigned)NBLK_S * (s + 1);
            while (atomicAdd(bar, 0u) < target) __nanosleep(32);
            __threadfence();
        }
        __syncthreads();
    }
}

/* ---- concat [hf0|hb0|hf1|hb1] rows, split bf16 output ----------------------- */
__global__ void concat4_split(const float* __restrict__ h0f,
                              const float* __restrict__ h1f,
                              bf* __restrict__ ob, bf* __restrict__ os,
                              int Nrows, int H, int KP) {
    long idx = blockIdx.x * 256L + threadIdx.x;
    int C = 4 * H;
    if (idx >= (long)Nrows * C) return;
    int c = (int)(idx % C);
    long n = idx / C;
    float v;
    if (c < 2 * H) {
        int d = c / H, hh = c % H;
        v = h0f[((long)d * Nrows + n) * KP + hh];
    } else {
        int c2 = c - 2 * H;
        int d = c2 / H, hh = c2 % H;
        v = h1f[((long)d * Nrows + n) * KP + hh];
    }
    bf vb, vs; bsplit(v, vb, vs);
    ob[idx] = vb; os[idx] = vs;
}

/* ---- concat fp32 (final output) --------------------------------------------- */
__global__ void concat4_k(const float* __restrict__ h0f, const float* __restrict__ h1f,
                          float* __restrict__ out, int Nrows, int H, int KP) {
    long idx = blockIdx.x * 256L + threadIdx.x;
    int C = 4 * H;
    if (idx >= (long)Nrows * C) return;
    int c = (int)(idx % C);
    long n = idx / C;
    float v;
    if (c < 2 * H) {
        int d = c / H, hh = c % H;
        v = h0f[((long)d * Nrows + n) * KP + hh];
    } else {
        int c2 = c - 2 * H;
        int d = c2 / H, hh = c2 % H;
        v = h1f[((long)d * Nrows + n) * KP + hh];
    }
    out[idx] = v;
}

/* ---------------------------------- host ------------------------------------ */
extern "C" void kernel_launch(void* const* d_in, const int* in_sizes, int n_in,
                              void* d_out, int out_size) {
    const int*   x        = (const int*)  d_in[0];
    const float* emb      = (const float*)d_in[1];
    const float* we_Wih0  = (const float*)d_in[2];
    const float* we_Whh0  = (const float*)d_in[3];
    const float* we_bih0  = (const float*)d_in[4];
    const float* we_bhh0  = (const float*)d_in[5];
    const float* we_Wih1  = (const float*)d_in[6];
    const float* we_Whh1  = (const float*)d_in[7];
    const float* we_bih1  = (const float*)d_in[8];
    const float* we_bhh1  = (const float*)d_in[9];
    const float* se_Wih0  = (const float*)d_in[10];
    const float* se_Whh0  = (const float*)d_in[11];
    const float* se_bih0  = (const float*)d_in[12];
    const float* se_bhh0  = (const float*)d_in[13];
    const float* se_Wih1  = (const float*)d_in[14];
    const float* se_Whh1  = (const float*)d_in[15];
    const float* se_bih1  = (const float*)d_in[16];
    const float* se_bhh1  = (const float*)d_in[17];
    (void)in_sizes; (void)n_in; (void)out_size;

    bf *xe_b, *xe_s, *y0w_b, *y0w_s, *words_b, *words_s, *y0s_b, *y0s_s;
    float *xw, *hwf, *hsf;
    bf *hwb, *hws, *hsb, *hss;
    unsigned* bar;
    bf *wW0b,*wW0s,*wW1b,*wW1s,*wH0b,*wH0s,*wH1b,*wH1s;
    bf *sW0b,*sW0s,*sW1b,*sW1s,*sH0b,*sH0s,*sH1b,*sH1s;
    cudaGetSymbolAddress((void**)&xe_b, g_xe_b);   cudaGetSymbolAddress((void**)&xe_s, g_xe_s);
    cudaGetSymbolAddress((void**)&xw, g_xw);
    cudaGetSymbolAddress((void**)&y0w_b, g_y0w_b); cudaGetSymbolAddress((void**)&y0w_s, g_y0w_s);
    cudaGetSymbolAddress((void**)&words_b, g_words_b); cudaGetSymbolAddress((void**)&words_s, g_words_s);
    cudaGetSymbolAddress((void**)&y0s_b, g_y0s_b); cudaGetSymbolAddress((void**)&y0s_s, g_y0s_s);
    cudaGetSymbolAddress((void**)&hwf, g_hwf);     cudaGetSymbolAddress((void**)&hsf, g_hsf);
    cudaGetSymbolAddress((void**)&hwb, g_hwb);     cudaGetSymbolAddress((void**)&hws, g_hws);
    cudaGetSymbolAddress((void**)&hsb, g_hsb);     cudaGetSymbolAddress((void**)&hss, g_hss);
    cudaGetSymbolAddress((void**)&bar, g_bar);
    cudaGetSymbolAddress((void**)&wW0b, g_weWih0_b); cudaGetSymbolAddress((void**)&wW0s, g_weWih0_s);
    cudaGetSymbolAddress((void**)&wW1b, g_weWih1_b); cudaGetSymbolAddress((void**)&wW1s, g_weWih1_s);
    cudaGetSymbolAddress((void**)&wH0b, g_weWhh0_b); cudaGetSymbolAddress((void**)&wH0s, g_weWhh0_s);
    cudaGetSymbolAddress((void**)&wH1b, g_weWhh1_b); cudaGetSymbolAddress((void**)&wH1s, g_weWhh1_s);
    cudaGetSymbolAddress((void**)&sW0b, g_seWih0_b); cudaGetSymbolAddress((void**)&sW0s, g_seWih0_s);
    cudaGetSymbolAddress((void**)&sW1b, g_seWih1_b); cudaGetSymbolAddress((void**)&sW1s, g_seWih1_s);
    cudaGetSymbolAddress((void**)&sH0b, g_seWhh0_b); cudaGetSymbolAddress((void**)&sH0s, g_seWhh0_s);
    cudaGetSymbolAddress((void**)&sH1b, g_seWhh1_b); cudaGetSymbolAddress((void**)&sH1s, g_seWhh1_s);

    cudaFuncSetAttribute(gru_sent_persistent,
                         cudaFuncAttributeMaxDynamicSharedMemorySize, SMEM_PERS);
    cudaFuncSetAttribute(mma_gemm_bias,
                         cudaFuncAttributeMaxDynamicSharedMemorySize, GEMM_SMEM);

    float* hwF[4]; bf* hwB[4]; bf* hwS[4];
    float* hsF[4]; bf* hsB[4]; bf* hsS[4];
    for (int i = 0; i < 4; i++) {
        hwF[i] = hwf + (long)i * HWBUF_N; hwB[i] = hwb + (long)i * HWBUF_N; hwS[i] = hws + (long)i * HWBUF_N;
        hsF[i] = hsf + (long)i * HSBUF_N; hsB[i] = hsb + (long)i * HSBUF_N; hsS[i] = hss + (long)i * HSBUF_N;
    }

    auto SPLIT = [](const float* w, bf* b, bf* s, int rows, int K, int KP) {
        long n = (long)rows * KP;
        split_k<<<(unsigned)((n + 255) / 256), 256>>>(w, b, s, rows, K, KP);
    };

    /* 0. split weights */
    SPLIT(we_Wih0, wW0b, wW0s, 2*3*HW, E_DIM, E_DIM);
    SPLIT(we_Wih1, wW1b, wW1s, 2*3*HW, 2*HW,  2*HW);
    SPLIT(we_Whh0, wH0b, wH0s, 2*3*HW, HW,    HWP);
    SPLIT(we_Whh1, wH1b, wH1s, 2*3*HW, HW,    HWP);
    SPLIT(se_Wih0, sW0b, sW0s, 2*3*HS, 4*HW,  4*HW);
    SPLIT(se_Wih1, sW1b, sW1s, 2*3*HS, 2*HS,  2*HS);
    SPLIT(se_Whh0, sH0b, sH0s, 2*3*HS, HS,    HS);
    SPLIT(se_Whh1, sH1b, sH1s, 2*3*HS, HS,    HS);

    /* 1. embedding (split) */
    embed_split_k<<<(XE_N + 255) / 256, 256>>>(x, emb, xe_b, xe_s);

    /* 2. word layer0: xw precompute + 10 steps (ys -> y0w split) */
    for (int d = 0; d < 2; d++) {
        dim3 g((3 * HW + 127) / 128, (T_LEN * NW) / 128);
        mma_gemm_bias<<<g, 256, GEMM_SMEM>>>(xe_b, xe_s,
                                  wW0b + (long)d * 3 * HW * E_DIM,
                                  wW0s + (long)d * 3 * HW * E_DIM,
                                  we_bih0 + d * 3 * HW,
                                  xw + (long)d * T_LEN * NW * 3 * HW,
                                  T_LEN * NW, 3 * HW, E_DIM);
    }
    cudaMemsetAsync(hwF[0], 0, sizeof(float) * HWBUF_N);
    cudaMemsetAsync(hwB[0], 0, sizeof(bf) * HWBUF_N);
    cudaMemsetAsync(hwS[0], 0, sizeof(bf) * HWBUF_N);
    {
        dim3 grid(2 * NW / 64, (HW + 15) / 16);
        for (int s = 0; s < T_LEN; s++) {
            int a = (s & 1), b = 1 - a;
            gru_step_mma<<<grid, 128>>>(hwF[a], hwB[a], hwS[a],
                                        hwF[b], hwB[b], hwS[b],
                                        xw, wH0b, wH0s, we_bhh0, y0w_b, y0w_s,
                                        HW, HWP, NW, T_LEN, s, T_LEN - 1 - s);
        }
    }

    /* 3. word layer1: xw from y0w + 10 steps (no ys) */
    for (int d = 0; d < 2; d++) {
        dim3 g((3 * HW + 127) / 128, (T_LEN * NW) / 128);
        mma_gemm_bias<<<g, 256, GEMM_SMEM>>>(y0w_b, y0w_s,
                                  wW1b + (long)d * 3 * HW * 2 * HW,
                                  wW1s + (long)d * 3 * HW * 2 * HW,
                                  we_bih1 + d * 3 * HW,
                                  xw + (long)d * T_LEN * NW * 3 * HW,
                                  T_LEN * NW, 3 * HW, 2 * HW);
    }
    cudaMemsetAsync(hwF[2], 0, sizeof(float) * HWBUF_N);
    cudaMemsetAsync(hwB[2], 0, sizeof(bf) * HWBUF_N);
    cudaMemsetAsync(hwS[2], 0, sizeof(bf) * HWBUF_N);
    {
        dim3 grid(2 * NW / 64, (HW + 15) / 16);
        for (int s = 0; s < T_LEN; s++) {
            int a = 2 + (s & 1), b = 2 + 1 - (s & 1);
            gru_step_mma<<<grid, 128>>>(hwF[a], hwB[a], hwS[a],
                                        hwF[b], hwB[b], hwS[b],
                                        xw, wH1b, wH1s, we_bhh1, (bf*)0, (bf*)0,
                                        HW, HWP, NW, T_LEN, s, T_LEN - 1 - s);
        }
    }

    /* 4. words = [hf0|hb0|hf1|hb1] split : [NW, 300] */
    concat4_split<<<(WORDS_N + 255) / 256, 256>>>(hwF[0], hwF[2],
                                                  words_b, words_s, NW, HW, HWP);

    /* 5. sentence layer0: xw precompute + persistent 120-step recurrence */
    for (int d = 0; d < 2; d++) {
        dim3 g((3 * HS + 127) / 128, (S_LEN * B_SZ) / 128);
        mma_gemm_bias<<<g, 256, GEMM_SMEM>>>(words_b, words_s,
                                  sW0b + (long)d * 3 * HS * 4 * HW,
                                  sW0s + (long)d * 3 * HS * 4 * HW,
                                  se_bih0 + d * 3 * HS,
                                  xw + (long)d * S_LEN * B_SZ * 3 * HS,
                                  S_LEN * B_SZ, 3 * HS, 4 * HW);
    }
    cudaMemsetAsync(hsF[0], 0, sizeof(float) * HSBUF_N);
    cudaMemsetAsync(hsB[0], 0, sizeof(bf) * HSBUF_N);
    cudaMemsetAsync(hsS[0], 0, sizeof(bf) * HSBUF_N);
    cudaMemsetAsync(bar, 0, sizeof(unsigned));
    gru_sent_persistent<<<NBLK_S, 256, SMEM_PERS>>>(
        sH0b, sH0s, se_bhh0, xw,
        hsF[0], hsB[0], hsS[0], hsF[1], hsB[1], hsS[1],
        y0s_b, y0s_s, bar);

    /* 6. sentence layer1: xw from y0s + persistent 120 steps (no ys) */
    for (int d = 0; d < 2; d++) {
        dim3 g((3 * HS + 127) / 128, (S_LEN * B_SZ) / 128);
        mma_gemm_bias<<<g, 256, GEMM_SMEM>>>(y0s_b, y0s_s,
                                  sW1b + (long)d * 3 * HS * 2 * HS,
                                  sW1s + (long)d * 3 * HS * 2 * HS,
                                  se_bih1 + d * 3 * HS,
                                  xw + (long)d * S_LEN * B_SZ * 3 * HS,
                                  S_LEN * B_SZ, 3 * HS, 2 * HS);
    }
    cudaMemsetAsync(hsF[2], 0, sizeof(float) * HSBUF_N);
    cudaMemsetAsync(hsB[2], 0, sizeof(bf) * HSBUF_N);
    cudaMemsetAsync(hsS[2], 0, sizeof(bf) * HSBUF_N);
    cudaMemsetAsync(bar, 0, sizeof(unsigned));
    gru_sent_persistent<<<NBLK_S, 256, SMEM_PERS>>>(
        sH1b, sH1s, se_bhh1, xw,
        hsF[2], hsB[2], hsS[2], hsF[3], hsB[3], hsS[3],
        (bf*)0, (bf*)0, bar);

    /* 7. output [1, 128, 2800] = [sf0|sb0|sf1|sb1] per batch row */
    concat4_k<<<((long)B_SZ * 4 * HS + 255) / 256, 256>>>(hsF[0], hsF[2],
                                                          (float*)d_out,
                                                          B_SZ, HS, HS);
}

// round 10
// speedup vs baseline: 1.1520x; 1.1520x over previous
#include <cuda_runtime.h>
#include <cuda_bf16.h>
#include <math.h>

#define S_LEN 120
#define T_LEN 10
#define B_SZ  128
#define E_DIM 80
#define HW    75
#define HWP   76
#define HS    700
#define NW    (S_LEN * B_SZ)   /* 15360 word-level batch */

typedef __nv_bfloat16 bf;

#define XE_N    (T_LEN * NW * E_DIM)
#define XW_N    (2L * T_LEN * NW * (3 * HW))
#define Y0W_N   (T_LEN * NW * 2 * HW)
#define WORDS_N (NW * 4 * HW)
#define Y0S_N   ((long)S_LEN * B_SZ * 2 * HS)
#define HWBUF_N (2 * NW * HWP)
#define HSBUF_N (2 * B_SZ * HS)

#define NBLK_S  88            /* persistent sentence kernel: 2 dirs x 44 hc tiles */
#define WSTRW   356           /* u32 stride of W smem row (356 % 32 == 4 -> conflict-free) */
#define SMEM_PERS (2 * 48 * WSTRW * 4)       /* 136704 B (no h staging anymore) */

#define GSTR    40            /* bf stride of GEMM smem row */
#define GEMM_SMEM (2 * 4 * 128 * GSTR * 2)   /* 81920 B */

/* ---------------- persistent scratch (device globals; no allocs) ------------- */
__device__ bf    g_xe_b[XE_N],    g_xe_s[XE_N];
__device__ float g_xw[XW_N];
__device__ bf    g_y0w_b[Y0W_N],  g_y0w_s[Y0W_N];
__device__ bf    g_words_b[WORDS_N], g_words_s[WORDS_N];
__device__ bf    g_y0s_b[Y0S_N],  g_y0s_s[Y0S_N];
__device__ float g_hwf[4][HWBUF_N];
__device__ bf    g_hwb[4][HWBUF_N], g_hws[4][HWBUF_N];
__device__ float g_hsf[4][HSBUF_N];
__device__ bf    g_hsb[4][HSBUF_N], g_hss[4][HSBUF_N];
__device__ unsigned g_bar;
/* weight splits */
__device__ bf g_weWih0_b[2*3*HW*E_DIM],  g_weWih0_s[2*3*HW*E_DIM];
__device__ bf g_weWih1_b[2*3*HW*2*HW],   g_weWih1_s[2*3*HW*2*HW];
__device__ bf g_weWhh0_b[2*3*HW*HWP],    g_weWhh0_s[2*3*HW*HWP];
__device__ bf g_weWhh1_b[2*3*HW*HWP],    g_weWhh1_s[2*3*HW*HWP];
__device__ bf g_seWih0_b[2*3*HS*4*HW],   g_seWih0_s[2*3*HS*4*HW];
__device__ bf g_seWih1_b[2*3*HS*2*HS],   g_seWih1_s[2*3*HS*2*HS];
__device__ bf g_seWhh0_b[2*3*HS*HS],     g_seWhh0_s[2*3*HS*HS];
__device__ bf g_seWhh1_b[2*3*HS*HS],     g_seWhh1_s[2*3*HS*HS];

/* ---------------- helpers ---------------------------------------------------- */
__device__ __forceinline__ void bsplit(float v, bf &b, bf &s) {
    b = __float2bfloat16_rn(v);
    s = __float2bfloat16_rn(v - __bfloat162float(b));
}
__device__ __forceinline__ void mma16(float d[4], const unsigned a[4],
                                      unsigned b0, unsigned b1) {
    asm volatile(
        "mma.sync.aligned.m16n8k16.row.col.f32.bf16.bf16.f32 "
        "{%0,%1,%2,%3},{%4,%5,%6,%7},{%8,%9},{%0,%1,%2,%3};"
        : "+f"(d[0]), "+f"(d[1]), "+f"(d[2]), "+f"(d[3])
        : "r"(a[0]), "r"(a[1]), "r"(a[2]), "r"(a[3]), "r"(b0), "r"(b1));
}
__device__ __forceinline__ void cpasync4(unsigned saddr, const void* g, bool p) {
    asm volatile("cp.async.ca.shared.global [%0], [%1], 4, %2;"
                 :: "r"(saddr), "l"(g), "r"(p ? 4u : 0u));
}
__device__ __forceinline__ void cp_commit() { asm volatile("cp.async.commit_group;"); }
__device__ __forceinline__ void cp_wait1()  { asm volatile("cp.async.wait_group 1;"); }
__device__ __forceinline__ void cp_wait0()  { asm volatile("cp.async.wait_group 0;"); }

/* ---------------- weight split: fp32 [rows,K] -> bf16 big/small [rows,KP] ---- */
__global__ void split_k(const float* __restrict__ W, bf* __restrict__ b,
                        bf* __restrict__ s, int rows, int K, int KP) {
    long idx = blockIdx.x * 256L + threadIdx.x;
    if (idx >= (long)rows * KP) return;
    int k = (int)(idx % KP);
    long r = idx / KP;
    float v = (k < K) ? W[r * K + k] : 0.f;
    bf vb, vs; bsplit(v, vb, vs);
    b[idx] = vb; s[idx] = vs;
}

/* ---------------- embedding gather + split ----------------------------------- */
__global__ void embed_split_k(const int* __restrict__ x, const float* __restrict__ emb,
                              bf* __restrict__ xb, bf* __restrict__ xs) {
    long idx = blockIdx.x * 256L + threadIdx.x;
    if (idx >= XE_N) return;
    int e = (int)(idx % E_DIM);
    int n = (int)((idx / E_DIM) % NW);
    int t = (int)(idx / ((long)E_DIM * NW));
    int s = n >> 7, bb_ = n & 127;
    int tok = x[(s * T_LEN + t) * B_SZ + bb_];
    float v = emb[(long)tok * E_DIM + e];
    bf vb, vs; bsplit(v, vb, vs);
    xb[idx] = vb; xs[idx] = vs;
}

/* -------- C[m][g] = bias[g] + A[m,:]·W[g,:]  (split A & W, 3-mma) ------------
   Tile 128x128, BK=32 bf, 256 thr (8 warps, 4x2). cp.async double-buffered. */
__global__ __launch_bounds__(256) void mma_gemm_bias(
    const bf* __restrict__ Ab_g, const bf* __restrict__ As_g,
    const bf* __restrict__ Wb_g, const bf* __restrict__ Ws_g,
    const float* __restrict__ bias, float* __restrict__ C,
    int M, int G, int K)
{
    extern __shared__ __align__(16) bf gsm[];   /* [2 buf][4 arr][128][GSTR] */
    unsigned sbase = (unsigned)__cvta_generic_to_shared(gsm);
    int tid = threadIdx.x, lane = tid & 31, wid = tid >> 5;
    int gid = lane >> 2, tig = lane & 3;
    int wm = wid & 3, wn = wid >> 2;
    int row0 = blockIdx.y * 128, col0 = blockIdx.x * 128;

    float acc[2][8][4];
#pragma unroll
    for (int mt = 0; mt < 2; mt++)
#pragma unroll
        for (int nt = 0; nt < 8; nt++)
#pragma unroll
            for (int i = 0; i < 4; i++) acc[mt][nt][i] = 0.f;

    auto fill = [&](int buf, int k0) {
#pragma unroll
        for (int j = 0; j < 32; j++) {
            int e = j * 256 + tid;
            int arr = e >> 11;
            int rem = e & 2047;
            int row = rem >> 4, kk = rem & 15;
            int gk = k0 + 2 * kk;
            unsigned sa = sbase + (unsigned)((((buf * 4 + arr) * 128 + row) * (GSTR/2) + kk) * 4);
            const bf* gp; bool v;
            if (arr < 2) {
                v = (gk < K) && (row0 + row < M);
                gp = (arr ? As_g : Ab_g) + (v ? ((long)(row0 + row) * K + gk) : 0);
            } else {
                int gc = col0 + row;
                v = (gk < K) && (gc < G);
                gp = (arr == 2 ? Wb_g : Ws_g) + (v ? ((long)gc * K + gk) : 0);
            }
            cpasync4(sa, gp, v);
        }
        cp_commit();
    };

    fill(0, 0);
    int buf = 0;
    for (int k0 = 0; k0 < K; k0 += 32) {
        bool more = (k0 + 32 < K);
        if (more) fill(1 - buf, k0 + 32);
        if (more) cp_wait1(); else cp_wait0();
        __syncthreads();

        const unsigned* sAb = (const unsigned*)(gsm + (long)(buf * 4 + 0) * 128 * GSTR);
        const unsigned* sAs = (const unsigned*)(gsm + (long)(buf * 4 + 1) * 128 * GSTR);
        const unsigned* sWb = (const unsigned*)(gsm + (long)(buf * 4 + 2) * 128 * GSTR);
        const unsigned* sWs = (const unsigned*)(gsm + (long)(buf * 4 + 3) * 128 * GSTR);
#pragma unroll
        for (int half = 0; half < 2; half++) {
            int base = half * 8;
            unsigned ab[2][4], as_[2][4];
#pragma unroll
            for (int mt = 0; mt < 2; mt++) {
                int mr = wm * 32 + mt * 16;
                const unsigned* p0b = sAb + (mr + gid) * (GSTR/2);
                const unsigned* p1b = sAb + (mr + gid + 8) * (GSTR/2);
                const unsigned* p0s = sAs + (mr + gid) * (GSTR/2);
                const unsigned* p1s = sAs + (mr + gid + 8) * (GSTR/2);
                ab[mt][0] = p0b[base + tig];      ab[mt][1] = p1b[base + tig];
                ab[mt][2] = p0b[base + tig + 4];  ab[mt][3] = p1b[base + tig + 4];
                as_[mt][0] = p0s[base + tig];     as_[mt][1] = p1s[base + tig];
                as_[mt][2] = p0s[base + tig + 4]; as_[mt][3] = p1s[base + tig + 4];
            }
#pragma unroll
            for (int nt = 0; nt < 8; nt++) {
                int nr = wn * 64 + nt * 8 + gid;
                const unsigned* pb = sWb + nr * (GSTR/2);
                const unsigned* ps = sWs + nr * (GSTR/2);
                unsigned bb0 = pb[base + tig], bb1 = pb[base + tig + 4];
                unsigned bs0 = ps[base + tig], bs1 = ps[base + tig + 4];
#pragma unroll
                for (int mt = 0; mt < 2; mt++) {
                    mma16(acc[mt][nt], ab[mt], bb0, bb1);
                    mma16(acc[mt][nt], ab[mt], bs0, bs1);
                    mma16(acc[mt][nt], as_[mt], bb0, bb1);
                }
            }
        }
        __syncthreads();
        buf = 1 - buf;
    }
#pragma unroll
    for (int mt = 0; mt < 2; mt++)
#pragma unroll
        for (int nt = 0; nt < 8; nt++)
#pragma unroll
            for (int i = 0; i < 4; i++) {
                int gr = row0 + wm * 32 + mt * 16 + gid + 8 * (i >> 1);
                int gc = col0 + wn * 64 + nt * 8 + tig * 2 + (i & 1);
                if (gr < M && gc < G)
                    C[(long)gr * G + gc] = acc[mt][nt][i] + bias[gc];
            }
}

/* -------- word GRU step: W staged once, h fragments loaded DIRECT from global,
   no syncthreads in the k-loop. 64 rows x 48 cols, 4 warps. ------------------- */
__global__ __launch_bounds__(128) void gru_step_mma(
    const float* __restrict__ hf_in, const bf* __restrict__ hb_in,
    const bf* __restrict__ hs_in,
    float* __restrict__ hf_out, bf* __restrict__ hb_out, bf* __restrict__ hs_out,
    const float* __restrict__ xw, const bf* __restrict__ Whh_b,
    const bf* __restrict__ Whh_s, const float* __restrict__ bhh,
    bf* __restrict__ y_b, bf* __restrict__ y_s,
    int H, int KP, int Nb, int T, int t_f, int t_b)
{
    __shared__ __align__(16) unsigned Wsm[2][48][44];  /* 44 % 32 == 12 -> conflict-free */
    int tid = threadIdx.x, lane = tid & 31, wid = tid >> 5;
    int gid = lane >> 2, tig = lane & 3;
    int r0 = blockIdx.x * 64;
    int dir = r0 / Nb;
    int n0 = r0 - dir * Nb;
    int h0 = blockIdx.y * 16;
    int KPW = KP >> 1;                    /* 38 u32 per h row */
    int mrow = wid * 16;

    /* stage W slice once: [2][48][44], zero-padded */
    for (int e = tid; e < 2 * 48 * 44; e += 128) {
        int arr = e / (48 * 44);
        int rem = e % (48 * 44);
        int r = rem / 44, w = rem % 44;
        int gate = r >> 4, hc = h0 + (r & 15);
        unsigned v = 0;
        if (w < KPW && hc < H) {
            const bf* src = (arr ? Whh_s : Whh_b) +
                            ((long)dir * 3 * H + (long)gate * H + hc) * KP + 2 * w;
            v = *(const unsigned*)src;
        }
        Wsm[arr][r][w] = v;
    }
    __syncthreads();

    const unsigned* r0b = (const unsigned*)hb_in + ((long)dir * Nb + n0 + mrow + gid) * KPW;
    const unsigned* r1b = r0b + 8 * KPW;
    const unsigned* r0s = (const unsigned*)hs_in + ((long)dir * Nb + n0 + mrow + gid) * KPW;
    const unsigned* r1s = r0s + 8 * KPW;

    float acc[6][4];
#pragma unroll
    for (int nt = 0; nt < 6; nt++)
#pragma unroll
        for (int i = 0; i < 4; i++) acc[nt][i] = 0.f;

    unsigned fa[2][8];
    auto loadf = [&](int it, unsigned (&f)[8]) {
        int c0 = it * 8 + tig;
        int c1 = c0 + 4;
        bool g = (c1 < 38);
        f[0] = r0b[c0];           f[1] = r1b[c0];
        f[2] = g ? r0b[c1] : 0u;  f[3] = g ? r1b[c1] : 0u;
        f[4] = r0s[c0];           f[5] = r1s[c0];
        f[6] = g ? r0s[c1] : 0u;  f[7] = g ? r1s[c1] : 0u;
    };
    loadf(0, fa[0]);
#pragma unroll
    for (int it = 0; it < 5; it++) {
        unsigned ab[4]  = {fa[it & 1][0], fa[it & 1][1], fa[it & 1][2], fa[it & 1][3]};
        unsigned as_[4] = {fa[it & 1][4], fa[it & 1][5], fa[it & 1][6], fa[it & 1][7]};
        if (it + 1 < 5) loadf(it + 1, fa[(it + 1) & 1]);
        int kb = it * 8;
#pragma unroll
        for (int nt = 0; nt < 6; nt++) {
            unsigned bb0 = Wsm[0][nt * 8 + gid][kb + tig];
            unsigned bb1 = Wsm[0][nt * 8 + gid][kb + tig + 4];
            unsigned bs0 = Wsm[1][nt * 8 + gid][kb + tig];
            unsigned bs1 = Wsm[1][nt * 8 + gid][kb + tig + 4];
            mma16(acc[nt], ab, bb0, bb1);
            mma16(acc[nt], ab, bs0, bs1);
            mma16(acc[nt], as_, bb0, bb1);
        }
    }

    int t = dir ? t_b : t_f;
#pragma unroll
    for (int nt = 0; nt < 2; nt++)
#pragma unroll
        for (int i = 0; i < 4; i++) {
            int n = n0 + mrow + gid + 8 * (i >> 1);
            int hc = h0 + nt * 8 + tig * 2 + (i & 1);
            if (hc >= H) continue;
            float br = bhh[dir * 3 * H + hc];
            float bz = bhh[dir * 3 * H + H + hc];
            float bn = bhh[dir * 3 * H + 2 * H + hc];
            long xb = ((long)(dir * T + t) * Nb + n) * (3 * H);
            float xr = xw[xb + hc];
            float xz = xw[xb + H + hc];
            float xn = xw[xb + 2 * H + hc];
            float gr_ = acc[nt][i] + br;
            float gz_ = acc[nt + 2][i] + bz;
            float gn_ = acc[nt + 4][i] + bn;
            float rg = 1.f / (1.f + expf(-(xr + gr_)));
            float zg = 1.f / (1.f + expf(-(xz + gz_)));
            float ng = tanhf(xn + rg * gn_);
            long hidx = ((long)dir * Nb + n) * KP + hc;
            float hp = hf_in[hidx];
            float hn = (1.f - zg) * ng + zg * hp;
            hf_out[hidx] = hn;
            bf hb_, hs_; bsplit(hn, hb_, hs_);
            hb_out[hidx] = hb_;
            hs_out[hidx] = hs_;
            if (y_b) {
                long yi = ((long)t * Nb + n) * 2 * H + (long)dir * H + hc;
                y_b[yi] = hb_; y_s[yi] = hs_;
            }
        }
}

/* -------- persistent sentence GRU: Whh in SMEM, h fragments DIRECT from
   global (sector-aligned), depth-2 register prefetch, no intra-step syncs. --- */
__global__ __launch_bounds__(256) void gru_sent_persistent(
    const bf* __restrict__ Whh_b, const bf* __restrict__ Whh_s,
    const float* __restrict__ bhh, const float* __restrict__ xw,
    float* __restrict__ hfA, bf* __restrict__ hbA, bf* __restrict__ hsA,
    float* __restrict__ hfB, bf* __restrict__ hbB, bf* __restrict__ hsB,
    bf* __restrict__ y_b, bf* __restrict__ y_s, unsigned* __restrict__ bar)
{
    extern __shared__ __align__(16) unsigned smem_u[];
    unsigned* Wu = smem_u;                       /* [2][48][WSTRW] */

    int tid = threadIdx.x, lane = tid & 31, wid = tid >> 5;
    int gid = lane >> 2, tig = lane & 3;
    int dir = blockIdx.x / 44;
    int h0 = (blockIdx.x % 44) * 16;
    int mrow = wid * 16;

    for (int e = tid; e < 2 * 48 * 352; e += 256) {
        int arr = e / (48 * 352);
        int rem = e % (48 * 352);
        int r = rem / 352, w = rem % 352;
        int gate = r >> 4, hc = h0 + (r & 15);
        unsigned v = 0;
        if (w < 350 && hc < HS) {
            const bf* src = (arr ? Whh_s : Whh_b) +
                            (((long)dir * 3 + gate) * HS + hc) * (long)HS + 2 * w;
            v = *(const unsigned*)src;
        }
        Wu[(long)arr * 48 * WSTRW + r * WSTRW + w] = v;
    }
    __syncthreads();

    for (int s = 0; s < S_LEN; s++) {
        const float* hf_in = (s & 1) ? hfB : hfA;
        const bf*    hb_in = (s & 1) ? hbB : hbA;
        const bf*    hs_in = (s & 1) ? hsB : hsA;
        float* hf_out = (s & 1) ? hfA : hfB;
        bf*    hb_out = (s & 1) ? hbA : hbB;
        bf*    hs_out = (s & 1) ? hsA : hsB;

        const unsigned* r0b = (const unsigned*)hb_in + ((long)dir * 128 + mrow + gid) * 350;
        const unsigned* r1b = r0b + 8 * 350;
        const unsigned* r0s = (const unsigned*)hs_in + ((long)dir * 128 + mrow + gid) * 350;
        const unsigned* r1s = r0s + 8 * 350;

        float acc[6][4];
#pragma unroll
        for (int nt = 0; nt < 6; nt++)
#pragma unroll
            for (int i = 0; i < 4; i++) acc[nt][i] = 0.f;

        unsigned fa0[8], fa1[8];
        auto loadf = [&](int it, unsigned (&f)[8]) {
            int c0 = it * 8 + tig;
            int c1 = c0 + 4;
            bool g = (c1 < 350);
            f[0] = r0b[c0];           f[1] = r1b[c0];
            f[2] = g ? r0b[c1] : 0u;  f[3] = g ? r1b[c1] : 0u;
            f[4] = r0s[c0];           f[5] = r1s[c0];
            f[6] = g ? r0s[c1] : 0u;  f[7] = g ? r1s[c1] : 0u;
        };
        auto step = [&](int it, unsigned (&f)[8]) {
            unsigned ab[4]  = {f[0], f[1], f[2], f[3]};
            unsigned as_[4] = {f[4], f[5], f[6], f[7]};
            if (it + 2 < 44) loadf(it + 2, f);     /* prefetch before mma block */
            int kb = it * 8;
#pragma unroll
            for (int nt = 0; nt < 6; nt++) {
                const unsigned* pb = Wu + (nt * 8 + gid) * WSTRW + kb;
                const unsigned* ps = pb + 48 * WSTRW;
                unsigned bb0 = pb[tig], bb1 = pb[tig + 4];
                unsigned bs0 = ps[tig], bs1 = ps[tig + 4];
                mma16(acc[nt], ab, bb0, bb1);
                mma16(acc[nt], ab, bs0, bs1);
                mma16(acc[nt], as_, bb0, bb1);
            }
        };
        loadf(0, fa0);
        loadf(1, fa1);
        for (int itp = 0; itp < 22; itp++) {
            step(itp * 2,     fa0);
            step(itp * 2 + 1, fa1);
        }

        int t = dir ? (S_LEN - 1 - s) : s;
#pragma unroll
        for (int nt = 0; nt < 2; nt++)
#pragma unroll
            for (int i = 0; i < 4; i++) {
                int n = mrow + gid + 8 * (i >> 1);
                int hc = h0 + nt * 8 + tig * 2 + (i & 1);
                if (hc >= HS) continue;
                float br = bhh[dir * 3 * HS + hc];
                float bz = bhh[dir * 3 * HS + HS + hc];
                float bn = bhh[dir * 3 * HS + 2 * HS + hc];
                long xb = ((long)(dir * S_LEN + t) * 128 + n) * (3 * HS);
                float xr = xw[xb + hc];
                float xz = xw[xb + HS + hc];
                float xn = xw[xb + 2 * HS + hc];
                float gr_ = acc[nt][i] + br;
                float gz_ = acc[nt + 2][i] + bz;
                float gn_ = acc[nt + 4][i] + bn;
                float rg = 1.f / (1.f + expf(-(xr + gr_)));
                float zg = 1.f / (1.f + expf(-(xz + gz_)));
                float ng = tanhf(xn + rg * gn_);
                long hidx = ((long)dir * 128 + n) * HS + hc;
                float hp = hf_in[hidx];
                float hn = (1.f - zg) * ng + zg * hp;
                hf_out[hidx] = hn;
                bf hb_, hs_; bsplit(hn, hb_, hs_);
                hb_out[hidx] = hb_;
                hs_out[hidx] = hs_;
                if (y_b) {
                    long yi = ((long)t * 128 + n) * 2 * HS + (long)dir * HS + hc;
                    y_b[yi] = hb_; y_s[yi] = hs_;
                }
            }

        /* grid barrier: all-thread fence (store visibility + L1 inval), then
           single-thread arrive + ld.cg spin. */
        __threadfence();
        __syncthreads();
        if (tid == 0) {
            atomicAdd(bar, 1u);
            unsigned target = (unsigned)NBLK_S * (s + 1);
            unsigned v;
            while (1) {
                asm volatile("ld.global.cg.u32 %0, [%1];" : "=r"(v) : "l"(bar));
                if (v >= target) break;
                __nanosleep(64);
            }
            __threadfence();               /* L1 invalidate before next-step reads */
        }
        __syncthreads();
    }
}

/* ---- concat [hf0|hb0|hf1|hb1] rows, split bf16 output ----------------------- */
__global__ void concat4_split(const float* __restrict__ h0f,
                              const float* __restrict__ h1f,
                              bf* __restrict__ ob, bf* __restrict__ os,
                              int Nrows, int H, int KP) {
    long idx = blockIdx.x * 256L + threadIdx.x;
    int C = 4 * H;
    if (idx >= (long)Nrows * C) return;
    int c = (int)(idx % C);
    long n = idx / C;
    float v;
    if (c < 2 * H) {
        int d = c / H, hh = c % H;
        v = h0f[((long)d * Nrows + n) * KP + hh];
    } else {
        int c2 = c - 2 * H;
        int d = c2 / H, hh = c2 % H;
        v = h1f[((long)d * Nrows + n) * KP + hh];
    }
    bf vb, vs; bsplit(v, vb, vs);
    ob[idx] = vb; os[idx] = vs;
}

/* ---- concat fp32 (final output) --------------------------------------------- */
__global__ void concat4_k(const float* __restrict__ h0f, const float* __restrict__ h1f,
                          float* __restrict__ out, int Nrows, int H, int KP) {
    long idx = blockIdx.x * 256L + threadIdx.x;
    int C = 4 * H;
    if (idx >= (long)Nrows * C) return;
    int c = (int)(idx % C);
    long n = idx / C;
    float v;
    if (c < 2 * H) {
        int d = c / H, hh = c % H;
        v = h0f[((long)d * Nrows + n) * KP + hh];
    } else {
        int c2 = c - 2 * H;
        int d = c2 / H, hh = c2 % H;
        v = h1f[((long)d * Nrows + n) * KP + hh];
    }
    out[idx] = v;
}

/* ---------------------------------- host ------------------------------------ */
extern "C" void kernel_launch(void* const* d_in, const int* in_sizes, int n_in,
                              void* d_out, int out_size) {
    const int*   x        = (const int*)  d_in[0];
    const float* emb      = (const float*)d_in[1];
    const float* we_Wih0  = (const float*)d_in[2];
    const float* we_Whh0  = (const float*)d_in[3];
    const float* we_bih0  = (const float*)d_in[4];
    const float* we_bhh0  = (const float*)d_in[5];
    const float* we_Wih1  = (const float*)d_in[6];
    const float* we_Whh1  = (const float*)d_in[7];
    const float* we_bih1  = (const float*)d_in[8];
    const float* we_bhh1  = (const float*)d_in[9];
    const float* se_Wih0  = (const float*)d_in[10];
    const float* se_Whh0  = (const float*)d_in[11];
    const float* se_bih0  = (const float*)d_in[12];
    const float* se_bhh0  = (const float*)d_in[13];
    const float* se_Wih1  = (const float*)d_in[14];
    const float* se_Whh1  = (const float*)d_in[15];
    const float* se_bih1  = (const float*)d_in[16];
    const float* se_bhh1  = (const float*)d_in[17];
    (void)in_sizes; (void)n_in; (void)out_size;

    bf *xe_b, *xe_s, *y0w_b, *y0w_s, *words_b, *words_s, *y0s_b, *y0s_s;
    float *xw, *hwf, *hsf;
    bf *hwb, *hws, *hsb, *hss;
    unsigned* bar;
    bf *wW0b,*wW0s,*wW1b,*wW1s,*wH0b,*wH0s,*wH1b,*wH1s;
    bf *sW0b,*sW0s,*sW1b,*sW1s,*sH0b,*sH0s,*sH1b,*sH1s;
    cudaGetSymbolAddress((void**)&xe_b, g_xe_b);   cudaGetSymbolAddress((void**)&xe_s, g_xe_s);
    cudaGetSymbolAddress((void**)&xw, g_xw);
    cudaGetSymbolAddress((void**)&y0w_b, g_y0w_b); cudaGetSymbolAddress((void**)&y0w_s, g_y0w_s);
    cudaGetSymbolAddress((void**)&words_b, g_words_b); cudaGetSymbolAddress((void**)&words_s, g_words_s);
    cudaGetSymbolAddress((void**)&y0s_b, g_y0s_b); cudaGetSymbolAddress((void**)&y0s_s, g_y0s_s);
    cudaGetSymbolAddress((void**)&hwf, g_hwf);     cudaGetSymbolAddress((void**)&hsf, g_hsf);
    cudaGetSymbolAddress((void**)&hwb, g_hwb);     cudaGetSymbolAddress((void**)&hws, g_hws);
    cudaGetSymbolAddress((void**)&hsb, g_hsb);     cudaGetSymbolAddress((void**)&hss, g_hss);
    cudaGetSymbolAddress((void**)&bar, g_bar);
    cudaGetSymbolAddress((void**)&wW0b, g_weWih0_b); cudaGetSymbolAddress((void**)&wW0s, g_weWih0_s);
    cudaGetSymbolAddress((void**)&wW1b, g_weWih1_b); cudaGetSymbolAddress((void**)&wW1s, g_weWih1_s);
    cudaGetSymbolAddress((void**)&wH0b, g_weWhh0_b); cudaGetSymbolAddress((void**)&wH0s, g_weWhh0_s);
    cudaGetSymbolAddress((void**)&wH1b, g_weWhh1_b); cudaGetSymbolAddress((void**)&wH1s, g_weWhh1_s);
    cudaGetSymbolAddress((void**)&sW0b, g_seWih0_b); cudaGetSymbolAddress((void**)&sW0s, g_seWih0_s);
    cudaGetSymbolAddress((void**)&sW1b, g_seWih1_b); cudaGetSymbolAddress((void**)&sW1s, g_seWih1_s);
    cudaGetSymbolAddress((void**)&sH0b, g_seWhh0_b); cudaGetSymbolAddress((void**)&sH0s, g_seWhh0_s);
    cudaGetSymbolAddress((void**)&sH1b, g_seWhh1_b); cudaGetSymbolAddress((void**)&sH1s, g_seWhh1_s);

    cudaFuncSetAttribute(gru_sent_persistent,
                         cudaFuncAttributeMaxDynamicSharedMemorySize, SMEM_PERS);
    cudaFuncSetAttribute(mma_gemm_bias,
                         cudaFuncAttributeMaxDynamicSharedMemorySize, GEMM_SMEM);

    float* hwF[4]; bf* hwB[4]; bf* hwS[4];
    float* hsF[4]; bf* hsB[4]; bf* hsS[4];
    for (int i = 0; i < 4; i++) {
        hwF[i] = hwf + (long)i * HWBUF_N; hwB[i] = hwb + (long)i * HWBUF_N; hwS[i] = hws + (long)i * HWBUF_N;
        hsF[i] = hsf + (long)i * HSBUF_N; hsB[i] = hsb + (long)i * HSBUF_N; hsS[i] = hss + (long)i * HSBUF_N;
    }

    auto SPLIT = [](const float* w, bf* b, bf* s, int rows, int K, int KP) {
        long n = (long)rows * KP;
        split_k<<<(unsigned)((n + 255) / 256), 256>>>(w, b, s, rows, K, KP);
    };

    /* 0. split weights */
    SPLIT(we_Wih0, wW0b, wW0s, 2*3*HW, E_DIM, E_DIM);
    SPLIT(we_Wih1, wW1b, wW1s, 2*3*HW, 2*HW,  2*HW);
    SPLIT(we_Whh0, wH0b, wH0s, 2*3*HW, HW,    HWP);
    SPLIT(we_Whh1, wH1b, wH1s, 2*3*HW, HW,    HWP);
    SPLIT(se_Wih0, sW0b, sW0s, 2*3*HS, 4*HW,  4*HW);
    SPLIT(se_Wih1, sW1b, sW1s, 2*3*HS, 2*HS,  2*HS);
    SPLIT(se_Whh0, sH0b, sH0s, 2*3*HS, HS,    HS);
    SPLIT(se_Whh1, sH1b, sH1s, 2*3*HS, HS,    HS);

    /* 1. embedding (split) */
    embed_split_k<<<(XE_N + 255) / 256, 256>>>(x, emb, xe_b, xe_s);

    /* 2. word layer0: xw precompute + 10 steps (ys -> y0w split) */
    for (int d = 0; d < 2; d++) {
        dim3 g((3 * HW + 127) / 128, (T_LEN * NW) / 128);
        mma_gemm_bias<<<g, 256, GEMM_SMEM>>>(xe_b, xe_s,
                                  wW0b + (long)d * 3 * HW * E_DIM,
                                  wW0s + (long)d * 3 * HW * E_DIM,
                                  we_bih0 + d * 3 * HW,
                                  xw + (long)d * T_LEN * NW * 3 * HW,
                                  T_LEN * NW, 3 * HW, E_DIM);
    }
    cudaMemsetAsync(hwF[0], 0, sizeof(float) * HWBUF_N);
    cudaMemsetAsync(hwB[0], 0, sizeof(bf) * HWBUF_N);
    cudaMemsetAsync(hwS[0], 0, sizeof(bf) * HWBUF_N);
    {
        dim3 grid(2 * NW / 64, (HW + 15) / 16);
        for (int s = 0; s < T_LEN; s++) {
            int a = (s & 1), b = 1 - a;
            gru_step_mma<<<grid, 128>>>(hwF[a], hwB[a], hwS[a],
                                        hwF[b], hwB[b], hwS[b],
                                        xw, wH0b, wH0s, we_bhh0, y0w_b, y0w_s,
                                        HW, HWP, NW, T_LEN, s, T_LEN - 1 - s);
        }
    }

    /* 3. word layer1: xw from y0w + 10 steps (no ys) */
    for (int d = 0; d < 2; d++) {
        dim3 g((3 * HW + 127) / 128, (T_LEN * NW) / 128);
        mma_gemm_bias<<<g, 256, GEMM_SMEM>>>(y0w_b, y0w_s,
                                  wW1b + (long)d * 3 * HW * 2 * HW,
                                  wW1s + (long)d * 3 * HW * 2 * HW,
                                  we_bih1 + d * 3 * HW,
                                  xw + (long)d * T_LEN * NW * 3 * HW,
                                  T_LEN * NW, 3 * HW, 2 * HW);
    }
    cudaMemsetAsync(hwF[2], 0, sizeof(float) * HWBUF_N);
    cudaMemsetAsync(hwB[2], 0, sizeof(bf) * HWBUF_N);
    cudaMemsetAsync(hwS[2], 0, sizeof(bf) * HWBUF_N);
    {
        dim3 grid(2 * NW / 64, (HW + 15) / 16);
        for (int s = 0; s < T_LEN; s++) {
            int a = 2 + (s & 1), b = 2 + 1 - (s & 1);
            gru_step_mma<<<grid, 128>>>(hwF[a], hwB[a], hwS[a],
                                        hwF[b], hwB[b], hwS[b],
                                        xw, wH1b, wH1s, we_bhh1, (bf*)0, (bf*)0,
                                        HW, HWP, NW, T_LEN, s, T_LEN - 1 - s);
        }
    }

    /* 4. words = [hf0|hb0|hf1|hb1] split : [NW, 300] */
    concat4_split<<<(WORDS_N + 255) / 256, 256>>>(hwF[0], hwF[2],
                                                  words_b, words_s, NW, HW, HWP);

    /* 5. sentence layer0: xw precompute + persistent 120-step recurrence */
    for (int d = 0; d < 2; d++) {
        dim3 g((3 * HS + 127) / 128, (S_LEN * B_SZ) / 128);
        mma_gemm_bias<<<g, 256, GEMM_SMEM>>>(words_b, words_s,
                                  sW0b + (long)d * 3 * HS * 4 * HW,
                                  sW0s + (long)d * 3 * HS * 4 * HW,
                                  se_bih0 + d * 3 * HS,
                                  xw + (long)d * S_LEN * B_SZ * 3 * HS,
                                  S_LEN * B_SZ, 3 * HS, 4 * HW);
    }
    cudaMemsetAsync(hsF[0], 0, sizeof(float) * HSBUF_N);
    cudaMemsetAsync(hsB[0], 0, sizeof(bf) * HSBUF_N);
    cudaMemsetAsync(hsS[0], 0, sizeof(bf) * HSBUF_N);
    cudaMemsetAsync(bar, 0, sizeof(unsigned));
    gru_sent_persistent<<<NBLK_S, 256, SMEM_PERS>>>(
        sH0b, sH0s, se_bhh0, xw,
        hsF[0], hsB[0], hsS[0], hsF[1], hsB[1], hsS[1],
        y0s_b, y0s_s, bar);

    /* 6. sentence layer1: xw from y0s + persistent 120 steps (no ys) */
    for (int d = 0; d < 2; d++) {
        dim3 g((3 * HS + 127) / 128, (S_LEN * B_SZ) / 128);
        mma_gemm_bias<<<g, 256, GEMM_SMEM>>>(y0s_b, y0s_s,
                                  sW1b + (long)d * 3 * HS * 2 * HS,
                                  sW1s + (long)d * 3 * HS * 2 * HS,
                                  se_bih1 + d * 3 * HS,
                                  xw + (long)d * S_LEN * B_SZ * 3 * HS,
                                  S_LEN * B_SZ, 3 * HS, 2 * HS);
    }
    cudaMemsetAsync(hsF[2], 0, sizeof(float) * HSBUF_N);
    cudaMemsetAsync(hsB[2], 0, sizeof(bf) * HSBUF_N);
    cudaMemsetAsync(hsS[2], 0, sizeof(bf) * HSBUF_N);
    cudaMemsetAsync(bar, 0, sizeof(unsigned));
    gru_sent_persistent<<<NBLK_S, 256, SMEM_PERS>>>(
        sH1b, sH1s, se_bhh1, xw,
        hsF[2], hsB[2], hsS[2], hsF[3], hsB[3], hsS[3],
        (bf*)0, (bf*)0, bar);

    /* 7. output [1, 128, 2800] = [sf0|sb0|sf1|sb1] per batch row */
    concat4_k<<<((long)B_SZ * 4 * HS + 255) / 256, 256>>>(hsF[0], hsF[2],
                                                          (float*)d_out,
                                                          B_SZ, HS, HS);
}